// round 8
// baseline (speedup 1.0000x reference)
#include <cuda_runtime.h>
#include <cuda_fp16.h>

#define N_VN    24576
#define D_V     4
#define D_C     8
#define E_EDGES (N_VN * D_V)     // 98304
#define M_CN    (E_EDGES / D_C)  // 12288
#define BSZ     64
#define CLIPV   20.0f
#define EPSV    1e-12f

#define PLANEU1 (N_VN * 32)      // uint (=half2) elements per plane
#define BUFU1   (4 * PLANEU1)    // uint elements per buffer (4 slots)

// ---------------- scratch (device globals: allocation-free) ----------------
__device__ float    g_llrT[N_VN * BSZ];       // llr transposed [vn][b]
__device__ unsigned g_c2v[2 * BUFU1];         // double-buffered [buf][slot][vn][b/2]
__device__ int      g_vn_edges[N_VN * D_V];   // vn -> its 4 edges (sorted)
__device__ int2     g_eidx[E_EDGES];          // edge -> {vn*32, slot*PLANEU1+vn*32}
__device__ int      g_vn_cnt[N_VN];

__device__ __forceinline__ float clipf(float v, float lo, float hi) {
    return fminf(fmaxf(v, lo), hi);
}
__device__ __forceinline__ __half2 h2(unsigned u) {
    return *reinterpret_cast<__half2*>(&u);
}

// tanh(0.5*v) = (e^v - 1)/(e^v + 1): keeps (1 - t) relatively accurate so the
// downstream atanh amplification near saturation cancels.
__device__ __forceinline__ float tanh_half(float v) {
    float e = __expf(v);
    return __fdividef(e - 1.0f, e + 1.0f);
}

__device__ __forceinline__ float cn_out(float p, float cw) {
    float o  = clipf(p, -0.999999f, 0.999999f);
    float lg = __logf(__fdividef(1.0f + o, (1.0f - o) + EPSV));
    float u  = clipf(lg, -CLIPV, CLIPV);
    return clipf(u * cw, -CLIPV, CLIPV);
}

// ------------- setup: transpose llr + zero cnt + zero c2v buf0 -------------
__global__ void k_setup(const float* __restrict__ in) {
    __shared__ float tile[BSZ * 33];
    int n0 = blockIdx.x * 32;
    int t = threadIdx.x;
#pragma unroll
    for (int k = 0; k < 8; k++) {       // load 32n x 64b tile (b-major source)
        int idx = t + k * 256;
        int nn = idx & 31, b = idx >> 5;
        tile[b * 33 + nn] = in[b * N_VN + n0 + nn];
    }
    if (t < 32) g_vn_cnt[n0 + t] = 0;
    {   // zero buffer 0 of c2v: 1024 uint4 per block x 768 blocks
        uint4* c4 = reinterpret_cast<uint4*>(g_c2v);
        int base = blockIdx.x * 1024;
#pragma unroll
        for (int k = 0; k < 4; k++)
            c4[base + t + k * 256] = make_uint4(0u, 0u, 0u, 0u);
    }
    __syncthreads();
#pragma unroll
    for (int k = 0; k < 8; k++) {
        int idx = t + k * 256;
        int b = idx & 63, nn = idx >> 6;
        g_llrT[(n0 + nn) * BSZ + b] = tile[b * 33 + nn];
    }
}

__global__ void k_build_inverse(const int* __restrict__ e2v) {
    int e = blockIdx.x * blockDim.x + threadIdx.x;
    if (e < E_EDGES) {
        int n = e2v[e];
        int pos = atomicAdd(&g_vn_cnt[n], 1);
        g_vn_edges[n * D_V + pos] = e;
    }
}

// sort each VN's 4 edges ascending (deterministic slots); emit index table
__global__ void k_sort4() {
    int n = blockIdx.x * blockDim.x + threadIdx.x;
    if (n >= N_VN) return;
    int* p = &g_vn_edges[n * 4];
    int a = p[0], b = p[1], c = p[2], d = p[3], x;
    if (a > b) { x = a; a = b; b = x; }
    if (c > d) { x = c; c = d; d = x; }
    if (a > c) { x = a; a = c; c = x; }
    if (b > d) { x = b; b = d; d = x; }
    if (b > c) { x = b; b = c; c = x; }
    p[0] = a; p[1] = b; p[2] = c; p[3] = d;
    int ro = n * 32;
    g_eidx[a] = make_int2(ro, 0 * PLANEU1 + ro);
    g_eidx[b] = make_int2(ro, 1 * PLANEU1 + ro);
    g_eidx[c] = make_int2(ro, 2 * PLANEU1 + ro);
    g_eidx[d] = make_int2(ro, 3 * PLANEU1 + ro);
}

// ------------- fused per-iteration kernel: belief-on-the-fly CN ------------
// One thread = one CN x 2 batch lanes (32 threads per CN). Reads buffer rb,
// writes buffer rb^1 (double buffer: no RAW race).
__global__ void __launch_bounds__(256, 4) k_cn(const float* __restrict__ cn_w,
                                               const float* __restrict__ ch_w,
                                               int it, int rb) {
    int idx = blockIdx.x * blockDim.x + threadIdx.x;   // M_CN * 32
    int cn = idx >> 5, qq = idx & 31;
    int ebase = cn * D_C;
    float cw  = __ldg(&cn_w[it]);
    float chw = __ldg(&ch_w[it]);
    const unsigned* rp = g_c2v + rb * BUFU1;
    unsigned*       wp = g_c2v + (rb ^ 1) * BUFU1;
    const float2* llr2 = reinterpret_cast<const float2*>(g_llrT);

    float2 t[D_C], p[D_C];
    int wof[D_C];
#pragma unroll
    for (int j = 0; j < D_C; j++) {
        int2 ix = __ldg(&g_eidx[ebase + j]);   // broadcast within warp
        int ro = ix.x + qq;
        wof[j] = ix.y + qq;
        unsigned u0 = rp[ro];
        unsigned u1 = rp[ro + PLANEU1];
        unsigned u2 = rp[ro + 2 * PLANEU1];
        unsigned u3 = rp[ro + 3 * PLANEU1];
        unsigned uo = rp[wof[j]];              // own c2v (no slot selects)
        // fp16 tree-sum of the 4 slot planes
        __half2 sA = __hadd2(__hadd2(h2(u0), h2(u1)), __hadd2(h2(u2), h2(u3)));
        float2 sa = __half22float2(sA);
        float2 oa = __half22float2(h2(uo));
        float2 L = llr2[ro];
        float vx = clipf(fmaf(L.x, chw, sa.x) - oa.x, -CLIPV, CLIPV);
        float vy = clipf(fmaf(L.y, chw, sa.y) - oa.y, -CLIPV, CLIPV);
        t[j].x = tanh_half(vx);
        t[j].y = tanh_half(vy);
        if (j == 0) {
            p[0] = make_float2(1.f, 1.f);
        } else {
            p[j].x = p[j - 1].x * t[j - 1].x;
            p[j].y = p[j - 1].y * t[j - 1].y;
        }
    }

    float2 S = make_float2(1.f, 1.f);
#pragma unroll
    for (int j = D_C - 1; j >= 0; j--) {
        float ex = p[j].x * S.x;
        float ey = p[j].y * S.y;
        __half2 h = __floats2half2_rn(cn_out(ex, cw), cn_out(ey, cw));
        wp[wof[j]] = *reinterpret_cast<unsigned*>(&h);
        S.x *= t[j].x;
        S.y *= t[j].y;
    }
}

// ---------------- final: dec = llr_in + sum c2v, transposed out ------------
__global__ void k_out(const float* __restrict__ in, float* __restrict__ out,
                      int fb) {
    __shared__ float tile[BSZ * 33];
    const __half* cv = reinterpret_cast<const __half*>(g_c2v + fb * BUFU1);
    int n0 = blockIdx.x * 32;
    int t = threadIdx.x;
#pragma unroll
    for (int k = 0; k < 8; k++) {       // b-fast mapping: coalesced plane reads
        int idx = t + k * 256;
        int b = idx & 63, nn = idx >> 6;
        int n = n0 + nn;
        float s = ((__half2float(cv[0 * N_VN * BSZ + n * BSZ + b]) +
                    __half2float(cv[1 * N_VN * BSZ + n * BSZ + b])) +
                    __half2float(cv[2 * N_VN * BSZ + n * BSZ + b])) +
                    __half2float(cv[3 * N_VN * BSZ + n * BSZ + b]);
        tile[b * 33 + nn] = s;
    }
    __syncthreads();
#pragma unroll
    for (int k = 0; k < 8; k++) {       // n-fast mapping: coalesced out writes
        int idx = t + k * 256;
        int nn = idx & 31, b = idx >> 5;
        out[b * N_VN + n0 + nn] = in[b * N_VN + n0 + nn] + tile[b * 33 + nn];
    }
}

// ---------------- launch ----------------
extern "C" void kernel_launch(void* const* d_in, const int* in_sizes, int n_in,
                              void* d_out, int out_size) {
    const float* llr  = (const float*)d_in[0];
    const float* cn_w = (const float*)d_in[1];
    const float* ch_w = (const float*)d_in[2];
    const int*   e2v  = (const int*)d_in[3];
    int iters = in_sizes[1];   // cn_weight length

    k_setup<<<N_VN / 32, 256>>>(llr);
    k_build_inverse<<<(E_EDGES + 255) / 256, 256>>>(e2v);
    k_sort4<<<(N_VN + 255) / 256, 256>>>();

    for (int it = 0; it < iters; it++)
        k_cn<<<(M_CN * 32) / 256, 256>>>(cn_w, ch_w, it, it & 1);

    k_out<<<N_VN / 32, 256>>>(llr, (float*)d_out, iters & 1);
}